// round 8
// baseline (speedup 1.0000x reference)
#include <cuda_runtime.h>
#include <cuda_bf16.h>
#include <math.h>
#include <stdint.h>

#define NB 2
#define NT 32
#define NI 2048
#define NF 64
#define TWOF 128
#define NL 5
#define TM1 31

#define RT_SIZE (NB*NI*TWOF)          // 524288
#define MT_OFF  RT_SIZE
#define LOSS_OFF (RT_SIZE + NB*TWOF)  // 524544

#define ES_STRIDE 68
#define ES_TILE   (32*ES_STRIDE)
#define SS_STRIDE 33

// ---------------- scratch (device globals: allocation-free) ----------------
__device__ __nv_bfloat16 g_rall[NB*NT*NI*TWOF];  // full r_all in bf16 (33.5MB)
__device__ float g_eta[NB*NT*NI];
__device__ float g_c[NI];
__device__ float g_W1T[TWOF*TWOF];               // sc_W1 transposed
__device__ unsigned char g_member[NT*NI];
__device__ int   g_cnt_pos[NB*TM1];
__device__ int   g_cnt_neg[NB*TM1];
__device__ float g_a1[NB*NT];
__device__ float g_a2[NB*NT];
__device__ float g_sync[NB*TM1];

__device__ __forceinline__ float warp_sum(float v){
  #pragma unroll
  for (int o = 16; o > 0; o >>= 1) v += __shfl_xor_sync(0xffffffffu, v, o);
  return v;
}

__device__ __forceinline__ uint32_t f2tf32(float x){
  uint32_t r;
  asm("cvt.rna.tf32.f32 %0, %1;" : "=r"(r) : "f"(x));
  return r;
}

__device__ __forceinline__ void mma_tf32(float c[4], const uint32_t a[4],
                                         uint32_t b0, uint32_t b1){
  asm("mma.sync.aligned.m16n8k8.row.col.f32.tf32.tf32.f32 "
      "{%0,%1,%2,%3},{%4,%5,%6,%7},{%8,%9},{%0,%1,%2,%3};"
      : "+f"(c[0]), "+f"(c[1]), "+f"(c[2]), "+f"(c[3])
      : "r"(a[0]), "r"(a[1]), "r"(a[2]), "r"(a[3]), "r"(b0), "r"(b1));
}

// ---------------- K_pre: iota dot + membership + counter zero + W1 transpose ----
__global__ void k_pre(const float* __restrict__ Wiota, const float* __restrict__ w_eta,
                      const int* __restrict__ perms, const float* __restrict__ sc_W1){
  int bx = blockIdx.x;
  int tid = threadIdx.x;
  if (bx < 8){
    int i = bx*256 + tid;
    float s = 0.f;
    const float4* wi = (const float4*)(Wiota + (size_t)i*TWOF);
    const float4* we = (const float4*)w_eta;
    #pragma unroll 8
    for (int q = 0; q < 32; q++){
      float4 a = wi[q], b = we[q];
      s += a.x*b.x + a.y*b.y + a.z*b.z + a.w*b.w;
    }
    g_c[i] = s;
  } else if (bx < 40){
    int t = bx - 8;
    for (int j = tid; j < NI; j += 256){
      int p = perms[t*NI + j];
      g_member[t*NI + p] = (unsigned char)(j >= NI/2);
    }
  } else if (bx == 40){
    if (tid < NB*TM1){ g_cnt_pos[tid] = 0; g_cnt_neg[tid] = 0; }
  } else {
    int base = (bx - 41) * 1024;
    #pragma unroll
    for (int q = 0; q < 4; q++){
      int x = base + q*256 + tid;
      int j = x >> 7, k = x & 127;
      g_W1T[k*TWOF + j] = sc_W1[x];
    }
  }
}

// ---------------- K_main: tf32-MMA k-GEMM + tf32-MMA scores + band softmax ----
__global__ __launch_bounds__(256) void k_main(
    const float* __restrict__ e_seq, const float* __restrict__ Ws_w,
    const float* __restrict__ Ws_b, const float* __restrict__ w_eta,
    const int* __restrict__ close_idx_p, float* __restrict__ d_out)
{
  __shared__ float smemA[64*ES_STRIDE];   // 17408B: Wsm -> Ks
  __shared__ float Esf[2*ES_TILE];        // 17408B
  __shared__ float Ss[2*32*SS_STRIDE];    //  8448B

  float* Wsm = smemA;
  float* Ks  = smemA;

  int i0 = blockIdx.x * 2, b = blockIdx.y;
  int tid = threadIdx.x;
  int warp = tid >> 5, lane = tid & 31;
  int g  = lane >> 2, tg = lane & 3;

  {
    const float4* wg = (const float4*)Ws_w;
    #pragma unroll
    for (int x = tid; x < 1024; x += 256){
      int fo = x >> 4, c = x & 15;
      ((float4*)(Wsm + fo*ES_STRIDE))[c] = wg[x];
    }
  }
  {
    #pragma unroll
    for (int x = tid; x < 1024; x += 256){
      int tile = x >> 9, t = (x >> 4) & 31, c = x & 15;
      const float4* eg = (const float4*)(e_seq + ((size_t)b*NT*NI + (i0+tile))*NF);
      ((float4*)(Esf + (tile*32 + t)*ES_STRIDE))[c] = eg[(size_t)t*(NI*16) + c];
    }
  }
  __syncthreads();

  if (warp < 2 && lane < TM1){
    int cidx = *close_idx_p;
    const float* ef = Esf + warp*ES_TILE;
    float c0 = ef[lane*ES_STRIDE + cidx];
    float c1 = ef[(lane+1)*ES_STRIDE + cidx];
    float r = c1 / (c0 + 1e-8f);
    if (r > 1.0f)      atomicAdd(&g_cnt_pos[b*TM1 + lane], 1);
    else if (r < 1.0f) atomicAdd(&g_cnt_neg[b*TM1 + lane], 1);
  }

  // ---- k = e @ Ws^T + b via tf32 mma, hi/lo split ----
  float c[4][4];
  {
    int tl = warp >> 2, mt = (warp >> 1) & 1, nh = warp & 1;
    const float* Et = Esf + tl*ES_TILE + (mt*16)*ES_STRIDE;

    #pragma unroll
    for (int nt = 0; nt < 4; nt++)
      #pragma unroll
      for (int q = 0; q < 4; q++) c[nt][q] = 0.f;

    #pragma unroll
    for (int ks = 0; ks < 8; ks++){
      int k0 = ks*8;
      float af[4];
      af[0] = Et[g*ES_STRIDE + k0 + tg];
      af[1] = Et[(g+8)*ES_STRIDE + k0 + tg];
      af[2] = Et[g*ES_STRIDE + k0 + tg + 4];
      af[3] = Et[(g+8)*ES_STRIDE + k0 + tg + 4];
      uint32_t ah[4], al[4];
      #pragma unroll
      for (int q = 0; q < 4; q++){
        ah[q] = f2tf32(af[q]);
        al[q] = f2tf32(af[q] - __uint_as_float(ah[q]));
      }
      #pragma unroll
      for (int nt = 0; nt < 4; nt++){
        int n0 = nh*32 + nt*8;
        float b0f = Wsm[(n0+g)*ES_STRIDE + k0 + tg];
        float b1f = Wsm[(n0+g)*ES_STRIDE + k0 + tg + 4];
        uint32_t bh0 = f2tf32(b0f), bh1 = f2tf32(b1f);
        uint32_t bl0 = f2tf32(b0f - __uint_as_float(bh0));
        uint32_t bl1 = f2tf32(b1f - __uint_as_float(bh1));
        mma_tf32(c[nt], ah, bh0, bh1);
        mma_tf32(c[nt], ah, bl0, bl1);
        mma_tf32(c[nt], al, bh0, bh1);
      }
    }
  }
  __syncthreads();

  {
    int tl = warp >> 2, mt = (warp >> 1) & 1, nh = warp & 1;
    #pragma unroll
    for (int nt = 0; nt < 4; nt++){
      int n0 = nh*32 + nt*8;
      int col = n0 + 2*tg;
      float bb0 = __ldg(Ws_b + col), bb1 = __ldg(Ws_b + col + 1);
      int r0 = mt*16 + g;
      float* k0p = Ks + (tl*32 + r0)*ES_STRIDE + col;
      float* k1p = Ks + (tl*32 + r0 + 8)*ES_STRIDE + col;
      k0p[0] = c[nt][0] + bb0; k0p[1] = c[nt][1] + bb1;
      k1p[0] = c[nt][2] + bb0; k1p[1] = c[nt][3] + bb1;
    }
  }
  __syncthreads();

  // ---- scores S = (K K^T)/8 per tile ----
  {
    int stile = warp >> 2;
    int smt   = (warp >> 1) & 1;
    int snh   = warp & 1;
    const float* Km = Ks + (stile*32 + smt*16)*ES_STRIDE;
    const float* Kn = Ks + stile*32*ES_STRIDE;

    float sc[2][4];
    #pragma unroll
    for (int u = 0; u < 2; u++)
      #pragma unroll
      for (int q = 0; q < 4; q++) sc[u][q] = 0.f;

    #pragma unroll
    for (int ks = 0; ks < 8; ks++){
      int k0 = ks*8;
      float af[4];
      af[0] = Km[g*ES_STRIDE + k0 + tg];
      af[1] = Km[(g+8)*ES_STRIDE + k0 + tg];
      af[2] = Km[g*ES_STRIDE + k0 + tg + 4];
      af[3] = Km[(g+8)*ES_STRIDE + k0 + tg + 4];
      uint32_t ah[4], al[4];
      #pragma unroll
      for (int q = 0; q < 4; q++){
        ah[q] = f2tf32(af[q]);
        al[q] = f2tf32(af[q] - __uint_as_float(ah[q]));
      }
      #pragma unroll
      for (int u = 0; u < 2; u++){
        int n0 = (2*snh + u)*8;
        float b0f = Kn[(n0+g)*ES_STRIDE + k0 + tg];
        float b1f = Kn[(n0+g)*ES_STRIDE + k0 + tg + 4];
        uint32_t bh0 = f2tf32(b0f), bh1 = f2tf32(b1f);
        uint32_t bl0 = f2tf32(b0f - __uint_as_float(bh0));
        uint32_t bl1 = f2tf32(b1f - __uint_as_float(bh1));
        mma_tf32(sc[u], ah, bh0, bh1);
        mma_tf32(sc[u], ah, bl0, bl1);
        mma_tf32(sc[u], al, bh0, bh1);
      }
    }
    #pragma unroll
    for (int u = 0; u < 2; u++){
      int col = (2*snh + u)*8 + 2*tg;
      int r0 = smt*16 + g;
      float* s0 = Ss + (stile*32 + r0)*SS_STRIDE + col;
      float* s1 = Ss + (stile*32 + r0 + 8)*SS_STRIDE + col;
      s0[0] = sc[u][0]*0.125f; s0[1] = sc[u][1]*0.125f;
      s1[0] = sc[u][2]*0.125f; s1[1] = sc[u][3]*0.125f;
    }
  }
  __syncthreads();

  float we0 = __ldg(w_eta + lane),      we1 = __ldg(w_eta + 32 + lane);
  float we2 = __ldg(w_eta + 64 + lane), we3 = __ldg(w_eta + 96 + lane);

  // ---- band softmax + r_all(bf16) + eta ----
  #pragma unroll
  for (int tile = 0; tile < 2; tile++){
    int i = i0 + tile;
    float ci = g_c[i];
    const float* Et = Esf + tile*ES_TILE;

    for (int tt = warp; tt < NT; tt += 8){
      const float* Srow = Ss + (tile*32 + tt)*SS_STRIDE;
      float s[NL];
      #pragma unroll
      for (int l = 0; l < NL; l++){
        int t2 = tt - 4 + l;
        s[l] = (t2 >= 0) ? Srow[t2] : -1e30f;
      }
      float mx = s[0];
      #pragma unroll
      for (int l = 1; l < NL; l++) mx = fmaxf(mx, s[l]);
      float pe[NL], psum = 0.f;
      #pragma unroll
      for (int l = 0; l < NL; l++){ pe[l] = expf(s[l] - mx); psum += pe[l]; }
      float inv = 1.0f / psum;
      float rh0 = 0.f, rh1 = 0.f;
      #pragma unroll
      for (int l = 0; l < NL; l++){
        int t2 = tt - 4 + l; if (t2 < 0) t2 = 0;
        float a = pe[l] * inv;
        rh0 += a * Et[t2*ES_STRIDE + lane];
        rh1 += a * Et[t2*ES_STRIDE + 32 + lane];
      }
      float e0 = Et[tt*ES_STRIDE + lane], e1 = Et[tt*ES_STRIDE + 32 + lane];

      __nv_bfloat16* rb = g_rall + (((size_t)b*NT + tt)*NI + i)*TWOF;
      rb[lane]      = __float2bfloat16(e0);
      rb[32 + lane] = __float2bfloat16(e1);
      rb[64 + lane] = __float2bfloat16(rh0);
      rb[96 + lane] = __float2bfloat16(rh1);

      float d = e0*we0 + e1*we1 + rh0*we2 + rh1*we3;
      d = warp_sum(d);
      float eta = fmaxf(d + ci, 0.f);
      if (lane == 0) g_eta[((size_t)b*NT + tt)*NI + i] = eta;

      if (tt == NT-1){
        float* ro = d_out + ((size_t)b*NI + i)*TWOF;
        ro[lane] = e0; ro[32+lane] = e1; ro[64+lane] = rh0; ro[96+lane] = rh1;
      }
    }
  }
}

// ---------------- K_tail: per-(b,t) masked sums + l2n + MLP + sync row ----------------
__global__ __launch_bounds__(512) void k_tail(
    const float* __restrict__ w_M,
    const float* __restrict__ sc_b1,
    const float* __restrict__ sc_W2, const float* __restrict__ sc_b2,
    float* __restrict__ d_out)
{
  int bt = blockIdx.x;
  int b = bt >> 5, t = bt & 31;
  int tid = threadIdx.x;
  int warp = tid >> 5, lane = tid & 31;

  __shared__ float eta_s[NI];       //  8KB  (sign encodes membership)
  __shared__ float redA[512*8];     // 16KB
  __shared__ float redB[512*8];     // 16KB
  __shared__ float ms[TWOF], hs[TWOF];
  __shared__ float part[32];
  __shared__ float dd[2];
  __shared__ float lg[3];

  // load eta, encode member in sign, accumulate dens
  float d1 = 0.f, d2 = 0.f;
  for (int i = tid; i < NI; i += 512){
    float e = g_eta[(size_t)bt*NI + i];
    bool m2 = g_member[t*NI + i];
    eta_s[i] = m2 ? -e : e;
    if (m2) d2 += e; else d1 += e;
  }
  d1 = warp_sum(d1);
  d2 = warp_sum(d2);
  if (lane == 0){ part[warp] = d1; part[16 + warp] = d2; }
  __syncthreads();
  if (tid == 0){
    float D1 = 0.f, D2 = 0.f;
    #pragma unroll
    for (int w = 0; w < 16; w++){ D1 += part[w]; D2 += part[16+w]; }
    dd[0] = D1; dd[1] = D2;
  }

  // masked sums over i: thread (jb = tid>>4 in 0..31, c = tid&15 chunk of 8 f)
  {
    int c  = tid & 15;
    int jb = tid >> 4;
    const uint4* base = (const uint4*)(g_rall + (size_t)bt*NI*TWOF);
    float a1[8], a2[8];
    #pragma unroll
    for (int q = 0; q < 8; q++){ a1[q] = 0.f; a2[q] = 0.f; }
    #pragma unroll 4
    for (int j = jb; j < NI; j += 32){
      uint4 v = base[(size_t)j*16 + c];
      float se = eta_s[j];
      float w1 = fmaxf(se, 0.f), w2 = fmaxf(-se, 0.f);
      float2 f0 = __bfloat1622float2(*(__nv_bfloat162*)&v.x);
      float2 f1 = __bfloat1622float2(*(__nv_bfloat162*)&v.y);
      float2 f2 = __bfloat1622float2(*(__nv_bfloat162*)&v.z);
      float2 f3 = __bfloat1622float2(*(__nv_bfloat162*)&v.w);
      a1[0] += w1*f0.x; a1[1] += w1*f0.y; a1[2] += w1*f1.x; a1[3] += w1*f1.y;
      a1[4] += w1*f2.x; a1[5] += w1*f2.y; a1[6] += w1*f3.x; a1[7] += w1*f3.y;
      a2[0] += w2*f0.x; a2[1] += w2*f0.y; a2[2] += w2*f1.x; a2[3] += w2*f1.y;
      a2[4] += w2*f2.x; a2[5] += w2*f2.y; a2[6] += w2*f3.x; a2[7] += w2*f3.y;
    }
    #pragma unroll
    for (int q = 0; q < 8; q++){
      redA[tid*8 + q] = a1[q];
      redB[tid*8 + q] = a2[q];
    }
  }
  __syncthreads();

  // combine: thread f (<128) sums 32 j-groups
  if (tid < TWOF){
    int c = tid >> 3, w = tid & 7;
    float n1 = 0.f, n2 = 0.f;
    #pragma unroll
    for (int g2 = 0; g2 < 32; g2++){
      int idx = (g2*16 + c)*8 + w;
      n1 += redA[idx];
      n2 += redB[idx];
    }
    float m1 = n1 / (dd[0] + 1e-6f);
    float m2 = n2 / (dd[1] + 1e-6f);
    float ma = (n1 + n2) / (dd[0] + dd[1] + 1e-6f);
    ms[tid] = ma;
    if (t == NT-1) d_out[MT_OFF + b*TWOF + tid] = ma;

    // l2n dots (4 warps among first 128 threads)
    float wm1 = w_M[tid], wm2 = w_M[TWOF + tid];
    float q0 = warp_sum(m1*m1);
    float q1 = warp_sum(m1*wm1);
    float q2 = warp_sum(m2*m2);
    float q3 = warp_sum(m2*wm2);
    if (lane == 0){
      part[warp] = q0; part[4+warp] = q1; part[8+warp] = q2; part[12+warp] = q3;
    }
  }
  __syncthreads();
  if (tid == 0){
    float sq1 = part[0]+part[1]+part[2]+part[3];
    float dt1 = part[4]+part[5]+part[6]+part[7];
    float sq2 = part[8]+part[9]+part[10]+part[11];
    float dt2 = part[12]+part[13]+part[14]+part[15];
    g_a1[bt] = dt1 / fmaxf(sqrtf(sq1), 1e-12f);
    g_a2[bt] = dt2 / fmaxf(sqrtf(sq2), 1e-12f);
  }

  // sync-loss row via pre-transposed W1 (coalesced, no shuffles)
  if (t < TM1){
    if (tid < TWOF){
      float acc = sc_b1[tid];
      #pragma unroll 16
      for (int k = 0; k < TWOF; k++)
        acc = fmaf(g_W1T[k*TWOF + tid], ms[k], acc);
      hs[tid] = fmaxf(acc, 0.f);
    }
    __syncthreads();
    if (warp < 3){
      float p = 0.f;
      #pragma unroll
      for (int q = 0; q < 4; q++)
        p += hs[lane + 32*q] * __ldg(&sc_W2[warp*TWOF + lane + 32*q]);
      p = warp_sum(p);
      if (lane == 0) lg[warp] = p + sc_b2[warp];
    }
    __syncthreads();
    if (tid == 0){
      int cp = g_cnt_pos[b*TM1 + t], cn = g_cnt_neg[b*TM1 + t];
      float pr = (float)cp * (1.0f/NI);
      float nr = (float)cn * (1.0f/NI);
      int lbl = (pr >= 0.6f) ? 0 : ((nr >= 0.6f) ? 1 : 2);
      float mx = fmaxf(lg[0], fmaxf(lg[1], lg[2]));
      float lse = logf(expf(lg[0]-mx) + expf(lg[1]-mx) + expf(lg[2]-mx)) + mx;
      g_sync[b*TM1 + t] = lse - lg[lbl];
    }
  }
}

// ---------------- K_final: contrast loss + combine ----------------
__global__ __launch_bounds__(256) void k_final(const float* __restrict__ b_M,
                                               float* __restrict__ d_out){
  int tid = threadIdx.x;
  __shared__ float red[256];
  float bm = *b_M;
  float acc = 0.f;
  if (tid < NT*NB){
    int t1 = tid & (NT-1), b = tid >> 5;
    float a1v = g_a1[b*NT + t1];
    float sum = 0.f, pos = 0.f;
    #pragma unroll 4
    for (int t2 = 0; t2 < NT; t2++){
      float sc = a1v + g_a2[b*NT + t2] + bm;
      sc = fminf(fmaxf(sc, -10.f), 10.f);
      float tw = 1.0f / (fabsf((float)(t1 - t2)) + 1.0f);
      float w = expf(sc * tw);
      sum += w;
      if (t2 == t1) pos = w;
    }
    acc = logf(sum + 1e-8f) - logf(pos);
  }
  red[tid] = acc; __syncthreads();
  for (int off = 128; off > 0; off >>= 1){
    if (tid < off) red[tid] += red[tid + off];
    __syncthreads();
  }
  float lc = red[0] * (1.0f/(NT*NB));
  __syncthreads();
  float sv = (tid < NB*TM1) ? g_sync[tid] : 0.f;
  red[tid] = sv; __syncthreads();
  for (int off = 128; off > 0; off >>= 1){
    if (tid < off) red[tid] += red[tid + off];
    __syncthreads();
  }
  if (tid == 0) d_out[LOSS_OFF] = lc + red[0] * (1.0f/(NB*TM1));
}

// ---------------- launch ----------------
extern "C" void kernel_launch(void* const* d_in, const int* in_sizes, int n_in,
                              void* d_out, int out_size){
  const float* e_seq = (const float*)d_in[0];
  const float* Ws_w  = (const float*)d_in[2];
  const float* Ws_b  = (const float*)d_in[3];
  const float* Wiota = (const float*)d_in[4];
  const float* w_eta = (const float*)d_in[5];
  const float* w_M   = (const float*)d_in[6];
  const float* b_M   = (const float*)d_in[7];
  const float* sc_W1 = (const float*)d_in[8];
  const float* sc_b1 = (const float*)d_in[9];
  const float* sc_W2 = (const float*)d_in[10];
  const float* sc_b2 = (const float*)d_in[11];
  const int*  perms  = (const int*)d_in[12];
  const int*  cidx   = (const int*)d_in[13];
  float* out = (float*)d_out;

  k_pre<<<57, 256>>>(Wiota, w_eta, perms, sc_W1);
  k_main<<<dim3(NI/2, NB), 256>>>(e_seq, Ws_w, Ws_b, w_eta, cidx, out);
  k_tail<<<NB*NT, 512>>>(w_M, sc_b1, sc_W2, sc_b2, out);
  k_final<<<1, 256>>>(b_M, out);
}

// round 9
// speedup vs baseline: 1.0657x; 1.0657x over previous
#include <cuda_runtime.h>
#include <cuda_bf16.h>
#include <math.h>
#include <stdint.h>

#define NB 2
#define NT 32
#define NI 2048
#define NF 64
#define TWOF 128
#define NL 5
#define NSPLIT 16
#define CHUNK 128
#define TM1 31
#define MP_STRIDE 264

#define RT_SIZE (NB*NI*TWOF)          // 524288
#define MT_OFF  RT_SIZE
#define LOSS_OFF (RT_SIZE + NB*TWOF)  // 524544

#define ES_STRIDE 68
#define ES_TILE   (32*ES_STRIDE)
#define SS_STRIDE 33

// ---------------- scratch (device globals: allocation-free) ----------------
__device__ __nv_bfloat16 g_rh[NB*NT*NI*NF];   // r_hist scratch (bf16)
__device__ float g_eta[NB*NT*NI];
__device__ float g_c[NI];
__device__ float g_W1T[TWOF*TWOF];            // sc_W1 transposed
__device__ unsigned char g_member[NT*NI];
__device__ int   g_cnt_pos[NB*TM1];
__device__ int   g_cnt_neg[NB*TM1];
__device__ float g_mpart[NB*NT*NSPLIT*MP_STRIDE];
__device__ float g_a1[NB*NT];
__device__ float g_a2[NB*NT];
__device__ float g_sync[NB*TM1];

__device__ __forceinline__ float warp_sum(float v){
  #pragma unroll
  for (int o = 16; o > 0; o >>= 1) v += __shfl_xor_sync(0xffffffffu, v, o);
  return v;
}

__device__ __forceinline__ uint32_t f2tf32(float x){
  uint32_t r;
  asm("cvt.rna.tf32.f32 %0, %1;" : "=r"(r) : "f"(x));
  return r;
}

__device__ __forceinline__ void mma_tf32(float c[4], const uint32_t a[4],
                                         uint32_t b0, uint32_t b1){
  asm("mma.sync.aligned.m16n8k8.row.col.f32.tf32.tf32.f32 "
      "{%0,%1,%2,%3},{%4,%5,%6,%7},{%8,%9},{%0,%1,%2,%3};"
      : "+f"(c[0]), "+f"(c[1]), "+f"(c[2]), "+f"(c[3])
      : "r"(a[0]), "r"(a[1]), "r"(a[2]), "r"(a[3]), "r"(b0), "r"(b1));
}

// ---------------- K_pre ----------------
__global__ void k_pre(const float* __restrict__ Wiota, const float* __restrict__ w_eta,
                      const int* __restrict__ perms, const float* __restrict__ sc_W1){
  int bx = blockIdx.x;
  int tid = threadIdx.x;
  if (bx < 8){
    int i = bx*256 + tid;
    float s = 0.f;
    const float4* wi = (const float4*)(Wiota + (size_t)i*TWOF);
    const float4* we = (const float4*)w_eta;
    #pragma unroll 8
    for (int q = 0; q < 32; q++){
      float4 a = wi[q], b = we[q];
      s += a.x*b.x + a.y*b.y + a.z*b.z + a.w*b.w;
    }
    g_c[i] = s;
  } else if (bx < 40){
    int t = bx - 8;
    for (int j = tid; j < NI; j += 256){
      int p = perms[t*NI + j];
      g_member[t*NI + p] = (unsigned char)(j >= NI/2);
    }
  } else if (bx == 40){
    if (tid < NB*TM1){ g_cnt_pos[tid] = 0; g_cnt_neg[tid] = 0; }
  } else {
    int base = (bx - 41) * 1024;
    #pragma unroll
    for (int q = 0; q < 4; q++){
      int x = base + q*256 + tid;
      int j = x >> 7, k = x & 127;
      g_W1T[k*TWOF + j] = sc_W1[x];
    }
  }
}

// ---------------- K_main: tf32-MMA k-GEMM (+eta columns) + MMA scores + band softmax ----
// smemA union: Ws (72x68) during GEMM, then K (64x68, cols 64/65 = eWa/eWb).
__global__ __launch_bounds__(256) void k_main(
    const float* __restrict__ e_seq, const float* __restrict__ Ws_w,
    const float* __restrict__ Ws_b, const float* __restrict__ w_eta,
    const int* __restrict__ close_idx_p, float* __restrict__ d_out)
{
  __shared__ float smemA[72*ES_STRIDE];   // 19584B: Wsm(72 rows) -> Ks(64 rows)
  __shared__ float Esf[2*ES_TILE];        // 17408B
  __shared__ float Ss[2*32*SS_STRIDE];    //  8448B

  float* Wsm = smemA;
  float* Ks  = smemA;

  int i0 = blockIdx.x * 2, b = blockIdx.y;
  int tid = threadIdx.x;
  int warp = tid >> 5, lane = tid & 31;
  int g  = lane >> 2, tg = lane & 3;

  // stage Ws rows 0-63
  {
    const float4* wg = (const float4*)Ws_w;
    #pragma unroll
    for (int x = tid; x < 1024; x += 256){
      int fo = x >> 4, c = x & 15;
      ((float4*)(Wsm + fo*ES_STRIDE))[c] = wg[x];
    }
  }
  // rows 64-71: 64 = w_eta[0:64], 65 = w_eta[64:128], 66-71 = 0
  {
    #pragma unroll
    for (int x = tid; x < 512; x += 256){
      int r = 64 + (x >> 6), f = x & 63;
      float v = 0.f;
      if (r == 64) v = w_eta[f];
      else if (r == 65) v = w_eta[64 + f];
      Wsm[r*ES_STRIDE + f] = v;
    }
  }
  // stage e for both tiles
  {
    #pragma unroll
    for (int x = tid; x < 1024; x += 256){
      int tile = x >> 9, t = (x >> 4) & 31, c = x & 15;
      const float4* eg = (const float4*)(e_seq + ((size_t)b*NT*NI + (i0+tile))*NF);
      ((float4*)(Esf + (tile*32 + t)*ES_STRIDE))[c] = eg[(size_t)t*(NI*16) + c];
    }
  }
  __syncthreads();

  // return-sign counts
  if (warp < 2 && lane < TM1){
    int cidx = *close_idx_p;
    const float* ef = Esf + warp*ES_TILE;
    float c0 = ef[lane*ES_STRIDE + cidx];
    float c1 = ef[(lane+1)*ES_STRIDE + cidx];
    float r = c1 / (c0 + 1e-8f);
    if (r > 1.0f)      atomicAdd(&g_cnt_pos[b*TM1 + lane], 1);
    else if (r < 1.0f) atomicAdd(&g_cnt_neg[b*TM1 + lane], 1);
  }

  // ---- k = e @ Ws^T (+ eta columns) via tf32 mma, hi/lo split ----
  float c[4][4];
  float ce[4];
  int tl = warp >> 2, mt = (warp >> 1) & 1, nh = warp & 1;
  {
    const float* Et = Esf + tl*ES_TILE + (mt*16)*ES_STRIDE;

    #pragma unroll
    for (int nt = 0; nt < 4; nt++)
      #pragma unroll
      for (int q = 0; q < 4; q++) c[nt][q] = 0.f;
    #pragma unroll
    for (int q = 0; q < 4; q++) ce[q] = 0.f;

    #pragma unroll
    for (int ks = 0; ks < 8; ks++){
      int k0 = ks*8;
      float af[4];
      af[0] = Et[g*ES_STRIDE + k0 + tg];
      af[1] = Et[(g+8)*ES_STRIDE + k0 + tg];
      af[2] = Et[g*ES_STRIDE + k0 + tg + 4];
      af[3] = Et[(g+8)*ES_STRIDE + k0 + tg + 4];
      uint32_t ah[4], al[4];
      #pragma unroll
      for (int q = 0; q < 4; q++){
        ah[q] = f2tf32(af[q]);
        al[q] = f2tf32(af[q] - __uint_as_float(ah[q]));
      }
      #pragma unroll
      for (int nt = 0; nt < 4; nt++){
        int n0 = nh*32 + nt*8;
        float b0f = Wsm[(n0+g)*ES_STRIDE + k0 + tg];
        float b1f = Wsm[(n0+g)*ES_STRIDE + k0 + tg + 4];
        uint32_t bh0 = f2tf32(b0f), bh1 = f2tf32(b1f);
        uint32_t bl0 = f2tf32(b0f - __uint_as_float(bh0));
        uint32_t bl1 = f2tf32(b1f - __uint_as_float(bh1));
        mma_tf32(c[nt], ah, bh0, bh1);
        mma_tf32(c[nt], ah, bl0, bl1);
        mma_tf32(c[nt], al, bh0, bh1);
      }
      if (nh == 0){
        float b0f = Wsm[(64+g)*ES_STRIDE + k0 + tg];
        float b1f = Wsm[(64+g)*ES_STRIDE + k0 + tg + 4];
        uint32_t bh0 = f2tf32(b0f), bh1 = f2tf32(b1f);
        uint32_t bl0 = f2tf32(b0f - __uint_as_float(bh0));
        uint32_t bl1 = f2tf32(b1f - __uint_as_float(bh1));
        mma_tf32(ce, ah, bh0, bh1);
        mma_tf32(ce, ah, bl0, bl1);
        mma_tf32(ce, al, bh0, bh1);
      }
    }
  }
  __syncthreads();   // done reading Wsm

  // bias + store K (cols 0-63) and eta columns (64/65) into union region
  {
    #pragma unroll
    for (int nt = 0; nt < 4; nt++){
      int n0 = nh*32 + nt*8;
      int col = n0 + 2*tg;
      float bb0 = __ldg(Ws_b + col), bb1 = __ldg(Ws_b + col + 1);
      int r0 = mt*16 + g;
      float* k0p = Ks + (tl*32 + r0)*ES_STRIDE + col;
      float* k1p = Ks + (tl*32 + r0 + 8)*ES_STRIDE + col;
      k0p[0] = c[nt][0] + bb0; k0p[1] = c[nt][1] + bb1;
      k1p[0] = c[nt][2] + bb0; k1p[1] = c[nt][3] + bb1;
    }
    if (nh == 0 && tg == 0){
      int r0 = mt*16 + g;
      float* k0p = Ks + (tl*32 + r0)*ES_STRIDE + 64;
      float* k1p = Ks + (tl*32 + r0 + 8)*ES_STRIDE + 64;
      k0p[0] = ce[0]; k0p[1] = ce[1];
      k1p[0] = ce[2]; k1p[1] = ce[3];
    }
  }
  __syncthreads();

  // ---- scores S = (K K^T)/8 per tile ----
  {
    int stile = warp >> 2;
    int smt   = (warp >> 1) & 1;
    int snh   = warp & 1;
    const float* Km = Ks + (stile*32 + smt*16)*ES_STRIDE;
    const float* Kn = Ks + stile*32*ES_STRIDE;

    float sc[2][4];
    #pragma unroll
    for (int u = 0; u < 2; u++)
      #pragma unroll
      for (int q = 0; q < 4; q++) sc[u][q] = 0.f;

    #pragma unroll
    for (int ks = 0; ks < 8; ks++){
      int k0 = ks*8;
      float af[4];
      af[0] = Km[g*ES_STRIDE + k0 + tg];
      af[1] = Km[(g+8)*ES_STRIDE + k0 + tg];
      af[2] = Km[g*ES_STRIDE + k0 + tg + 4];
      af[3] = Km[(g+8)*ES_STRIDE + k0 + tg + 4];
      uint32_t ah[4], al[4];
      #pragma unroll
      for (int q = 0; q < 4; q++){
        ah[q] = f2tf32(af[q]);
        al[q] = f2tf32(af[q] - __uint_as_float(ah[q]));
      }
      #pragma unroll
      for (int u = 0; u < 2; u++){
        int n0 = (2*snh + u)*8;
        float b0f = Kn[(n0+g)*ES_STRIDE + k0 + tg];
        float b1f = Kn[(n0+g)*ES_STRIDE + k0 + tg + 4];
        uint32_t bh0 = f2tf32(b0f), bh1 = f2tf32(b1f);
        uint32_t bl0 = f2tf32(b0f - __uint_as_float(bh0));
        uint32_t bl1 = f2tf32(b1f - __uint_as_float(bh1));
        mma_tf32(sc[u], ah, bh0, bh1);
        mma_tf32(sc[u], ah, bl0, bl1);
        mma_tf32(sc[u], al, bh0, bh1);
      }
    }
    #pragma unroll
    for (int u = 0; u < 2; u++){
      int col = (2*snh + u)*8 + 2*tg;
      int r0 = smt*16 + g;
      float* s0 = Ss + (stile*32 + r0)*SS_STRIDE + col;
      float* s1 = Ss + (stile*32 + r0 + 8)*SS_STRIDE + col;
      s0[0] = sc[u][0]*0.125f; s0[1] = sc[u][1]*0.125f;
      s1[0] = sc[u][2]*0.125f; s1[1] = sc[u][3]*0.125f;
    }
  }
  __syncthreads();

  // ---- band softmax + r_hist + eta (no reductions at all) ----
  #pragma unroll
  for (int tile = 0; tile < 2; tile++){
    int i = i0 + tile;
    float ci = g_c[i];
    const float* Et = Esf + tile*ES_TILE;
    const float* Kt = Ks  + (tile*32)*ES_STRIDE;

    for (int tt = warp; tt < NT; tt += 8){
      const float* Srow = Ss + (tile*32 + tt)*SS_STRIDE;
      float s[NL];
      #pragma unroll
      for (int l = 0; l < NL; l++){
        int t2 = tt - 4 + l;
        s[l] = (t2 >= 0) ? Srow[t2] : -1e30f;
      }
      float mx = s[0];
      #pragma unroll
      for (int l = 1; l < NL; l++) mx = fmaxf(mx, s[l]);
      float pe[NL], psum = 0.f;
      #pragma unroll
      for (int l = 0; l < NL; l++){ pe[l] = __expf(s[l] - mx); psum += pe[l]; }
      float inv = 1.0f / psum;
      float rh0 = 0.f, rh1 = 0.f;
      float dsum = Kt[tt*ES_STRIDE + 64];   // eWa[tt]
      #pragma unroll
      for (int l = 0; l < NL; l++){
        int t2 = tt - 4 + l; if (t2 < 0) t2 = 0;
        float a = pe[l] * inv;
        rh0 += a * Et[t2*ES_STRIDE + lane];
        rh1 += a * Et[t2*ES_STRIDE + 32 + lane];
        dsum += a * Kt[t2*ES_STRIDE + 65];  // a_l * eWb[tl]
      }
      size_t rbase = (((size_t)b*NT + tt)*NI + i)*NF;
      g_rh[rbase + lane]      = __float2bfloat16(rh0);
      g_rh[rbase + 32 + lane] = __float2bfloat16(rh1);

      float eta = fmaxf(dsum + ci, 0.f);
      if (lane == 0) g_eta[((size_t)b*NT + tt)*NI + i] = eta;

      if (tt == NT-1){
        float e0 = Et[tt*ES_STRIDE + lane], e1 = Et[tt*ES_STRIDE + 32 + lane];
        float* ro = d_out + ((size_t)b*NI + i)*TWOF;
        ro[lane] = e0; ro[32+lane] = e1; ro[64+lane] = rh0; ro[96+lane] = rh1;
      }
    }
  }
}

// ---------------- K_msum: masked partial sums of eta * r_all + dens ----------------
__global__ __launch_bounds__(128) void k_msum(const float* __restrict__ e_seq){
  int bt = blockIdx.x;
  int t  = bt % NT;
  int s  = blockIdx.y;
  int tid = threadIdx.x;
  __shared__ float eta_s[CHUNK];
  __shared__ float w2_s[CHUNK];
  __shared__ float4 red[256];
  int i0 = s * CHUNK;
  if (tid < CHUNK){
    float e = g_eta[(size_t)bt*NI + i0 + tid];
    eta_s[tid] = e;
    w2_s[tid]  = g_member[t*NI + i0 + tid] ? e : 0.f;
  }
  __syncthreads();

  int fq = tid & 31;
  int jb = tid >> 5;
  bool hi = fq >= 16;
  int c = hi ? fq - 16 : fq;
  float4 a1 = make_float4(0.f,0.f,0.f,0.f);
  float4 a2 = make_float4(0.f,0.f,0.f,0.f);

  if (!hi){
    const float4* base = (const float4*)(e_seq + ((size_t)bt*NI + i0)*NF);
    #pragma unroll 8
    for (int j = jb; j < CHUNK; j += 4){
      float4 r = base[(size_t)j*16 + c];
      float w2 = w2_s[j], w1 = eta_s[j] - w2;
      a1.x += w1*r.x; a1.y += w1*r.y; a1.z += w1*r.z; a1.w += w1*r.w;
      a2.x += w2*r.x; a2.y += w2*r.y; a2.z += w2*r.z; a2.w += w2*r.w;
    }
  } else {
    const __nv_bfloat162* base =
        (const __nv_bfloat162*)(g_rh + ((size_t)bt*NI + i0)*NF);
    #pragma unroll 8
    for (int j = jb; j < CHUNK; j += 4){
      __nv_bfloat162 p0 = base[(size_t)j*32 + 2*c];
      __nv_bfloat162 p1 = base[(size_t)j*32 + 2*c + 1];
      float4 r;
      r.x = __bfloat162float(p0.x); r.y = __bfloat162float(p0.y);
      r.z = __bfloat162float(p1.x); r.w = __bfloat162float(p1.y);
      float w2 = w2_s[j], w1 = eta_s[j] - w2;
      a1.x += w1*r.x; a1.y += w1*r.y; a1.z += w1*r.z; a1.w += w1*r.w;
      a2.x += w2*r.x; a2.y += w2*r.y; a2.z += w2*r.z; a2.w += w2*r.w;
    }
  }
  red[tid] = a1; red[128 + tid] = a2;
  __syncthreads();

  float* op = g_mpart + ((size_t)bt*NSPLIT + s)*MP_STRIDE;
  if (tid < 64){
    int which = tid >> 5;
    int q = tid & 31;
    float4 sum = red[which*128 + q];
    #pragma unroll
    for (int g2 = 1; g2 < 4; g2++){
      float4 v = red[which*128 + 32*g2 + q];
      sum.x += v.x; sum.y += v.y; sum.z += v.z; sum.w += v.w;
    }
    ((float4*)(op + which*TWOF))[q] = sum;
  } else if (tid < 96){
    int l = tid - 64;
    float d1 = 0.f, d2 = 0.f;
    #pragma unroll
    for (int j = l; j < CHUNK; j += 32){ float w2 = w2_s[j]; d2 += w2; d1 += eta_s[j] - w2; }
    d1 = warp_sum(d1);
    d2 = warp_sum(d2);
    if (l == 0){ op[2*TWOF] = d1; op[2*TWOF+1] = d2; }
  }
}

// ---------------- K_mfinal ----------------
__global__ __launch_bounds__(128) void k_mfinal(
    const float* __restrict__ w_M,
    const float* __restrict__ sc_b1,
    const float* __restrict__ sc_W2, const float* __restrict__ sc_b2,
    float* __restrict__ d_out)
{
  int bt = blockIdx.x;
  int b = bt / NT, t = bt % NT;
  int tid = threadIdx.x;
  int warp = tid >> 5, lane = tid & 31;
  __shared__ float ms[TWOF];
  __shared__ float hs[TWOF];
  __shared__ float part[16];
  __shared__ float dd[2];
  __shared__ float lg[3];

  float n1 = 0.f, n2 = 0.f;
  #pragma unroll
  for (int s = 0; s < NSPLIT; s++){
    const float* p = g_mpart + ((size_t)bt*NSPLIT + s)*MP_STRIDE;
    n1 += p[tid];
    n2 += p[TWOF + tid];
  }
  if (tid < 16){
    const float* p = g_mpart + ((size_t)bt*NSPLIT + tid)*MP_STRIDE;
    float d1 = p[2*TWOF], d2 = p[2*TWOF+1];
    #pragma unroll
    for (int o = 8; o > 0; o >>= 1){
      d1 += __shfl_down_sync(0xffffu, d1, o);
      d2 += __shfl_down_sync(0xffffu, d2, o);
    }
    if (tid == 0){ dd[0] = d1; dd[1] = d2; }
  }
  __syncthreads();

  float m1 = n1 / (dd[0] + 1e-6f);
  float m2 = n2 / (dd[1] + 1e-6f);
  float ma = (n1 + n2) / (dd[0] + dd[1] + 1e-6f);
  ms[tid] = ma;
  if (t == NT-1) d_out[MT_OFF + b*TWOF + tid] = ma;

  float wm1 = w_M[tid], wm2 = w_M[TWOF + tid];
  float q0 = warp_sum(m1*m1);
  float q1 = warp_sum(m1*wm1);
  float q2 = warp_sum(m2*m2);
  float q3 = warp_sum(m2*wm2);
  if (lane == 0){
    part[warp] = q0; part[4+warp] = q1; part[8+warp] = q2; part[12+warp] = q3;
  }
  __syncthreads();
  if (tid == 0){
    float sq1 = part[0]+part[1]+part[2]+part[3];
    float dt1 = part[4]+part[5]+part[6]+part[7];
    float sq2 = part[8]+part[9]+part[10]+part[11];
    float dt2 = part[12]+part[13]+part[14]+part[15];
    g_a1[bt] = dt1 / fmaxf(sqrtf(sq1), 1e-12f);
    g_a2[bt] = dt2 / fmaxf(sqrtf(sq2), 1e-12f);
  }

  if (t < TM1){
    float acc = sc_b1[tid];
    #pragma unroll 16
    for (int k = 0; k < TWOF; k++)
      acc = fmaf(g_W1T[k*TWOF + tid], ms[k], acc);
    hs[tid] = fmaxf(acc, 0.f);
    __syncthreads();
    if (warp < 3){
      float p = 0.f;
      #pragma unroll
      for (int q = 0; q < 4; q++)
        p += hs[lane + 32*q] * __ldg(&sc_W2[warp*TWOF + lane + 32*q]);
      p = warp_sum(p);
      if (lane == 0) lg[warp] = p + sc_b2[warp];
    }
    __syncthreads();
    if (tid == 0){
      int cp = g_cnt_pos[b*TM1 + t], cn = g_cnt_neg[b*TM1 + t];
      float pr = (float)cp * (1.0f/NI);
      float nr = (float)cn * (1.0f/NI);
      int lbl = (pr >= 0.6f) ? 0 : ((nr >= 0.6f) ? 1 : 2);
      float mx = fmaxf(lg[0], fmaxf(lg[1], lg[2]));
      float lse = __logf(__expf(lg[0]-mx) + __expf(lg[1]-mx) + __expf(lg[2]-mx)) + mx;
      g_sync[b*TM1 + t] = lse - lg[lbl];
    }
  }
}

// ---------------- K_final ----------------
__global__ __launch_bounds__(256) void k_final(const float* __restrict__ b_M,
                                               float* __restrict__ d_out){
  int tid = threadIdx.x;
  __shared__ float red[256];
  float bm = *b_M;
  float acc = 0.f;
  if (tid < NT*NB){
    int t1 = tid & (NT-1), b = tid >> 5;
    float a1v = g_a1[b*NT + t1];
    float sum = 0.f, pos = 0.f;
    #pragma unroll 4
    for (int t2 = 0; t2 < NT; t2++){
      float sc = a1v + g_a2[b*NT + t2] + bm;
      sc = fminf(fmaxf(sc, -10.f), 10.f);
      float tw = 1.0f / (fabsf((float)(t1 - t2)) + 1.0f);
      float w = __expf(sc * tw);
      sum += w;
      if (t2 == t1) pos = w;
    }
    acc = __logf(sum + 1e-8f) - __logf(pos);
  }
  red[tid] = acc; __syncthreads();
  for (int off = 128; off > 0; off >>= 1){
    if (tid < off) red[tid] += red[tid + off];
    __syncthreads();
  }
  float lc = red[0] * (1.0f/(NT*NB));
  __syncthreads();
  float sv = (tid < NB*TM1) ? g_sync[tid] : 0.f;
  red[tid] = sv; __syncthreads();
  for (int off = 128; off > 0; off >>= 1){
    if (tid < off) red[tid] += red[tid + off];
    __syncthreads();
  }
  if (tid == 0) d_out[LOSS_OFF] = lc + red[0] * (1.0f/(NB*TM1));
}

// ---------------- launch ----------------
extern "C" void kernel_launch(void* const* d_in, const int* in_sizes, int n_in,
                              void* d_out, int out_size){
  const float* e_seq = (const float*)d_in[0];
  const float* Ws_w  = (const float*)d_in[2];
  const float* Ws_b  = (const float*)d_in[3];
  const float* Wiota = (const float*)d_in[4];
  const float* w_eta = (const float*)d_in[5];
  const float* w_M   = (const float*)d_in[6];
  const float* b_M   = (const float*)d_in[7];
  const float* sc_W1 = (const float*)d_in[8];
  const float* sc_b1 = (const float*)d_in[9];
  const float* sc_W2 = (const float*)d_in[10];
  const float* sc_b2 = (const float*)d_in[11];
  const int*  perms  = (const int*)d_in[12];
  const int*  cidx   = (const int*)d_in[13];
  float* out = (float*)d_out;

  k_pre<<<57, 256>>>(Wiota, w_eta, perms, sc_W1);
  k_main<<<dim3(NI/2, NB), 256>>>(e_seq, Ws_w, Ws_b, w_eta, cidx, out);
  k_msum<<<dim3(NB*NT, NSPLIT), 128>>>(e_seq);
  k_mfinal<<<NB*NT, 128>>>(w_M, sc_b1, sc_W2, sc_b2, out);
  k_final<<<1, 256>>>(b_M, out);
}

// round 10
// speedup vs baseline: 1.0895x; 1.0223x over previous
#include <cuda_runtime.h>
#include <cuda_bf16.h>
#include <math.h>
#include <stdint.h>

#define NB 2
#define NT 32
#define NI 2048
#define NF 64
#define TWOF 128
#define NL 5
#define NSPLIT 16
#define CHUNK 128
#define TM1 31
#define MP_STRIDE 264

#define RT_SIZE (NB*NI*TWOF)          // 524288
#define MT_OFF  RT_SIZE
#define LOSS_OFF (RT_SIZE + NB*TWOF)  // 524544

#define ES_STRIDE 68
#define ES_TILE   (32*ES_STRIDE)
#define SS_STRIDE 33

// ---------------- scratch (device globals: allocation-free) ----------------
__device__ __nv_bfloat16 g_rh[NB*NT*NI*NF];   // r_hist scratch (bf16)
__device__ float g_eta[NB*NT*NI];
__device__ float g_c[NI];
__device__ float g_W1T[TWOF*TWOF];            // sc_W1 transposed
__device__ unsigned char g_member[NT*NI];
__device__ int   g_cnt_pos[NB*TM1];
__device__ int   g_cnt_neg[NB*TM1];
__device__ float g_mpart[NB*NT*NSPLIT*MP_STRIDE];
__device__ float g_a1[NB*NT];
__device__ float g_a2[NB*NT];
__device__ float g_sync[NB*TM1];
__device__ int   g_done_bt[NB*NT];
__device__ int   g_done_all;

__device__ __forceinline__ float warp_sum(float v){
  #pragma unroll
  for (int o = 16; o > 0; o >>= 1) v += __shfl_xor_sync(0xffffffffu, v, o);
  return v;
}

__device__ __forceinline__ uint32_t f2tf32(float x){
  uint32_t r;
  asm("cvt.rna.tf32.f32 %0, %1;" : "=r"(r) : "f"(x));
  return r;
}

__device__ __forceinline__ void mma_tf32(float c[4], const uint32_t a[4],
                                         uint32_t b0, uint32_t b1){
  asm("mma.sync.aligned.m16n8k8.row.col.f32.tf32.tf32.f32 "
      "{%0,%1,%2,%3},{%4,%5,%6,%7},{%8,%9},{%0,%1,%2,%3};"
      : "+f"(c[0]), "+f"(c[1]), "+f"(c[2]), "+f"(c[3])
      : "r"(a[0]), "r"(a[1]), "r"(a[2]), "r"(a[3]), "r"(b0), "r"(b1));
}

// ---------------- K_pre ----------------
__global__ void k_pre(const float* __restrict__ Wiota, const float* __restrict__ w_eta,
                      const int* __restrict__ perms, const float* __restrict__ sc_W1){
  int bx = blockIdx.x;
  int tid = threadIdx.x;
  if (bx < 8){
    int i = bx*256 + tid;
    float s = 0.f;
    const float4* wi = (const float4*)(Wiota + (size_t)i*TWOF);
    const float4* we = (const float4*)w_eta;
    #pragma unroll 8
    for (int q = 0; q < 32; q++){
      float4 a = wi[q], b = we[q];
      s += a.x*b.x + a.y*b.y + a.z*b.z + a.w*b.w;
    }
    g_c[i] = s;
  } else if (bx < 40){
    int t = bx - 8;
    for (int j = tid; j < NI; j += 256){
      int p = perms[t*NI + j];
      g_member[t*NI + p] = (unsigned char)(j >= NI/2);
    }
  } else if (bx == 40){
    if (tid < NB*TM1){ g_cnt_pos[tid] = 0; g_cnt_neg[tid] = 0; }
    if (tid >= 64 && tid < 64 + NB*NT) g_done_bt[tid - 64] = 0;
    if (tid == 128) g_done_all = 0;
  } else {
    int base = (bx - 41) * 1024;
    #pragma unroll
    for (int q = 0; q < 4; q++){
      int x = base + q*256 + tid;
      int j = x >> 7, k = x & 127;
      g_W1T[k*TWOF + j] = sc_W1[x];
    }
  }
}

// ---------------- K_main (R7 version): tf32-MMA k-GEMM + MMA scores + band softmax ----
__global__ __launch_bounds__(256) void k_main(
    const float* __restrict__ e_seq, const float* __restrict__ Ws_w,
    const float* __restrict__ Ws_b, const float* __restrict__ w_eta,
    const int* __restrict__ close_idx_p, float* __restrict__ d_out)
{
  __shared__ float smemA[64*ES_STRIDE];   // 17408B: Wsm -> Ks
  __shared__ float Esf[2*ES_TILE];        // 17408B
  __shared__ float Ss[2*32*SS_STRIDE];    //  8448B

  float* Wsm = smemA;
  float* Ks  = smemA;

  int i0 = blockIdx.x * 2, b = blockIdx.y;
  int tid = threadIdx.x;
  int warp = tid >> 5, lane = tid & 31;
  int g  = lane >> 2, tg = lane & 3;

  {
    const float4* wg = (const float4*)Ws_w;
    #pragma unroll
    for (int x = tid; x < 1024; x += 256){
      int fo = x >> 4, c = x & 15;
      ((float4*)(Wsm + fo*ES_STRIDE))[c] = wg[x];
    }
  }
  {
    #pragma unroll
    for (int x = tid; x < 1024; x += 256){
      int tile = x >> 9, t = (x >> 4) & 31, c = x & 15;
      const float4* eg = (const float4*)(e_seq + ((size_t)b*NT*NI + (i0+tile))*NF);
      ((float4*)(Esf + (tile*32 + t)*ES_STRIDE))[c] = eg[(size_t)t*(NI*16) + c];
    }
  }
  __syncthreads();

  if (warp < 2 && lane < TM1){
    int cidx = *close_idx_p;
    const float* ef = Esf + warp*ES_TILE;
    float c0 = ef[lane*ES_STRIDE + cidx];
    float c1 = ef[(lane+1)*ES_STRIDE + cidx];
    float r = c1 / (c0 + 1e-8f);
    if (r > 1.0f)      atomicAdd(&g_cnt_pos[b*TM1 + lane], 1);
    else if (r < 1.0f) atomicAdd(&g_cnt_neg[b*TM1 + lane], 1);
  }

  // ---- k = e @ Ws^T + b via tf32 mma, hi/lo split ----
  float c[4][4];
  {
    int tl = warp >> 2, mt = (warp >> 1) & 1, nh = warp & 1;
    const float* Et = Esf + tl*ES_TILE + (mt*16)*ES_STRIDE;

    #pragma unroll
    for (int nt = 0; nt < 4; nt++)
      #pragma unroll
      for (int q = 0; q < 4; q++) c[nt][q] = 0.f;

    #pragma unroll
    for (int ks = 0; ks < 8; ks++){
      int k0 = ks*8;
      float af[4];
      af[0] = Et[g*ES_STRIDE + k0 + tg];
      af[1] = Et[(g+8)*ES_STRIDE + k0 + tg];
      af[2] = Et[g*ES_STRIDE + k0 + tg + 4];
      af[3] = Et[(g+8)*ES_STRIDE + k0 + tg + 4];
      uint32_t ah[4], al[4];
      #pragma unroll
      for (int q = 0; q < 4; q++){
        ah[q] = f2tf32(af[q]);
        al[q] = f2tf32(af[q] - __uint_as_float(ah[q]));
      }
      #pragma unroll
      for (int nt = 0; nt < 4; nt++){
        int n0 = nh*32 + nt*8;
        float b0f = Wsm[(n0+g)*ES_STRIDE + k0 + tg];
        float b1f = Wsm[(n0+g)*ES_STRIDE + k0 + tg + 4];
        uint32_t bh0 = f2tf32(b0f), bh1 = f2tf32(b1f);
        uint32_t bl0 = f2tf32(b0f - __uint_as_float(bh0));
        uint32_t bl1 = f2tf32(b1f - __uint_as_float(bh1));
        mma_tf32(c[nt], ah, bh0, bh1);
        mma_tf32(c[nt], ah, bl0, bl1);
        mma_tf32(c[nt], al, bh0, bh1);
      }
    }
  }
  __syncthreads();

  {
    int tl = warp >> 2, mt = (warp >> 1) & 1, nh = warp & 1;
    #pragma unroll
    for (int nt = 0; nt < 4; nt++){
      int n0 = nh*32 + nt*8;
      int col = n0 + 2*tg;
      float bb0 = __ldg(Ws_b + col), bb1 = __ldg(Ws_b + col + 1);
      int r0 = mt*16 + g;
      float* k0p = Ks + (tl*32 + r0)*ES_STRIDE + col;
      float* k1p = Ks + (tl*32 + r0 + 8)*ES_STRIDE + col;
      k0p[0] = c[nt][0] + bb0; k0p[1] = c[nt][1] + bb1;
      k1p[0] = c[nt][2] + bb0; k1p[1] = c[nt][3] + bb1;
    }
  }
  __syncthreads();

  // ---- scores S = (K K^T)/8 per tile ----
  {
    int stile = warp >> 2;
    int smt   = (warp >> 1) & 1;
    int snh   = warp & 1;
    const float* Km = Ks + (stile*32 + smt*16)*ES_STRIDE;
    const float* Kn = Ks + stile*32*ES_STRIDE;

    float sc[2][4];
    #pragma unroll
    for (int u = 0; u < 2; u++)
      #pragma unroll
      for (int q = 0; q < 4; q++) sc[u][q] = 0.f;

    #pragma unroll
    for (int ks = 0; ks < 8; ks++){
      int k0 = ks*8;
      float af[4];
      af[0] = Km[g*ES_STRIDE + k0 + tg];
      af[1] = Km[(g+8)*ES_STRIDE + k0 + tg];
      af[2] = Km[g*ES_STRIDE + k0 + tg + 4];
      af[3] = Km[(g+8)*ES_STRIDE + k0 + tg + 4];
      uint32_t ah[4], al[4];
      #pragma unroll
      for (int q = 0; q < 4; q++){
        ah[q] = f2tf32(af[q]);
        al[q] = f2tf32(af[q] - __uint_as_float(ah[q]));
      }
      #pragma unroll
      for (int u = 0; u < 2; u++){
        int n0 = (2*snh + u)*8;
        float b0f = Kn[(n0+g)*ES_STRIDE + k0 + tg];
        float b1f = Kn[(n0+g)*ES_STRIDE + k0 + tg + 4];
        uint32_t bh0 = f2tf32(b0f), bh1 = f2tf32(b1f);
        uint32_t bl0 = f2tf32(b0f - __uint_as_float(bh0));
        uint32_t bl1 = f2tf32(b1f - __uint_as_float(bh1));
        mma_tf32(sc[u], ah, bh0, bh1);
        mma_tf32(sc[u], ah, bl0, bl1);
        mma_tf32(sc[u], al, bh0, bh1);
      }
    }
    #pragma unroll
    for (int u = 0; u < 2; u++){
      int col = (2*snh + u)*8 + 2*tg;
      int r0 = smt*16 + g;
      float* s0 = Ss + (stile*32 + r0)*SS_STRIDE + col;
      float* s1 = Ss + (stile*32 + r0 + 8)*SS_STRIDE + col;
      s0[0] = sc[u][0]*0.125f; s0[1] = sc[u][1]*0.125f;
      s1[0] = sc[u][2]*0.125f; s1[1] = sc[u][3]*0.125f;
    }
  }
  __syncthreads();

  float we0 = __ldg(w_eta + lane),      we1 = __ldg(w_eta + 32 + lane);
  float we2 = __ldg(w_eta + 64 + lane), we3 = __ldg(w_eta + 96 + lane);

  #pragma unroll
  for (int tile = 0; tile < 2; tile++){
    int i = i0 + tile;
    float ci = g_c[i];
    const float* Et = Esf + tile*ES_TILE;

    for (int tt = warp; tt < NT; tt += 8){
      const float* Srow = Ss + (tile*32 + tt)*SS_STRIDE;
      float s[NL];
      #pragma unroll
      for (int l = 0; l < NL; l++){
        int t2 = tt - 4 + l;
        s[l] = (t2 >= 0) ? Srow[t2] : -1e30f;
      }
      float mx = s[0];
      #pragma unroll
      for (int l = 1; l < NL; l++) mx = fmaxf(mx, s[l]);
      float pe[NL], psum = 0.f;
      #pragma unroll
      for (int l = 0; l < NL; l++){ pe[l] = expf(s[l] - mx); psum += pe[l]; }
      float inv = 1.0f / psum;
      float rh0 = 0.f, rh1 = 0.f;
      #pragma unroll
      for (int l = 0; l < NL; l++){
        int t2 = tt - 4 + l; if (t2 < 0) t2 = 0;
        float a = pe[l] * inv;
        rh0 += a * Et[t2*ES_STRIDE + lane];
        rh1 += a * Et[t2*ES_STRIDE + 32 + lane];
      }
      size_t rbase = (((size_t)b*NT + tt)*NI + i)*NF;
      g_rh[rbase + lane]      = __float2bfloat16(rh0);
      g_rh[rbase + 32 + lane] = __float2bfloat16(rh1);

      float e0 = Et[tt*ES_STRIDE + lane], e1 = Et[tt*ES_STRIDE + 32 + lane];
      float d = e0*we0 + e1*we1 + rh0*we2 + rh1*we3;
      d = warp_sum(d);
      float eta = fmaxf(d + ci, 0.f);
      if (lane == 0) g_eta[((size_t)b*NT + tt)*NI + i] = eta;

      if (tt == NT-1){
        float* ro = d_out + ((size_t)b*NI + i)*TWOF;
        ro[lane] = e0; ro[32+lane] = e1; ro[64+lane] = rh0; ro[96+lane] = rh1;
      }
    }
  }
}

// ---------------- K_msum + fused tail ----------------
__global__ __launch_bounds__(128) void k_msum(
    const float* __restrict__ e_seq,
    const float* __restrict__ w_M,
    const float* __restrict__ sc_b1,
    const float* __restrict__ sc_W2, const float* __restrict__ sc_b2,
    const float* __restrict__ b_M,
    float* __restrict__ d_out)
{
  int bt = blockIdx.x;
  int b = bt / NT, t = bt % NT;
  int s  = blockIdx.y;
  int tid = threadIdx.x;
  int warp = tid >> 5, lane = tid & 31;
  __shared__ float eta_s[CHUNK];
  __shared__ float w2_s[CHUNK];
  __shared__ float4 red[256];             // 4KB, reused by tail phases
  __shared__ int flags[2];
  float* redf = (float*)red;              // 1024 floats

  int i0 = s * CHUNK;
  if (tid < CHUNK){
    float e = g_eta[(size_t)bt*NI + i0 + tid];
    eta_s[tid] = e;
    w2_s[tid]  = g_member[t*NI + i0 + tid] ? e : 0.f;
  }
  __syncthreads();

  int fq = tid & 31;
  int jb = tid >> 5;
  bool hi = fq >= 16;
  int c = hi ? fq - 16 : fq;
  float4 a1 = make_float4(0.f,0.f,0.f,0.f);
  float4 a2 = make_float4(0.f,0.f,0.f,0.f);

  if (!hi){
    const float4* base = (const float4*)(e_seq + ((size_t)bt*NI + i0)*NF);
    #pragma unroll 8
    for (int j = jb; j < CHUNK; j += 4){
      float4 r = base[(size_t)j*16 + c];
      float w2 = w2_s[j], w1 = eta_s[j] - w2;
      a1.x += w1*r.x; a1.y += w1*r.y; a1.z += w1*r.z; a1.w += w1*r.w;
      a2.x += w2*r.x; a2.y += w2*r.y; a2.z += w2*r.z; a2.w += w2*r.w;
    }
  } else {
    const __nv_bfloat162* base =
        (const __nv_bfloat162*)(g_rh + ((size_t)bt*NI + i0)*NF);
    #pragma unroll 8
    for (int j = jb; j < CHUNK; j += 4){
      __nv_bfloat162 p0 = base[(size_t)j*32 + 2*c];
      __nv_bfloat162 p1 = base[(size_t)j*32 + 2*c + 1];
      float4 r;
      r.x = __bfloat162float(p0.x); r.y = __bfloat162float(p0.y);
      r.z = __bfloat162float(p1.x); r.w = __bfloat162float(p1.y);
      float w2 = w2_s[j], w1 = eta_s[j] - w2;
      a1.x += w1*r.x; a1.y += w1*r.y; a1.z += w1*r.z; a1.w += w1*r.w;
      a2.x += w2*r.x; a2.y += w2*r.y; a2.z += w2*r.z; a2.w += w2*r.w;
    }
  }
  red[tid] = a1; red[128 + tid] = a2;
  __syncthreads();

  float* op = g_mpart + ((size_t)bt*NSPLIT + s)*MP_STRIDE;
  if (tid < 64){
    int which = tid >> 5;
    int q = tid & 31;
    float4 sum = red[which*128 + q];
    #pragma unroll
    for (int g2 = 1; g2 < 4; g2++){
      float4 v = red[which*128 + 32*g2 + q];
      sum.x += v.x; sum.y += v.y; sum.z += v.z; sum.w += v.w;
    }
    ((float4*)(op + which*TWOF))[q] = sum;
  } else if (tid < 96){
    int l = tid - 64;
    float d1 = 0.f, d2 = 0.f;
    #pragma unroll
    for (int j = l; j < CHUNK; j += 32){ float w2 = w2_s[j]; d2 += w2; d1 += eta_s[j] - w2; }
    d1 = warp_sum(d1);
    d2 = warp_sum(d2);
    if (l == 0){ op[2*TWOF] = d1; op[2*TWOF+1] = d2; }
  }

  // ---- release partials; last block per bt does the combine ----
  __syncthreads();
  __threadfence();
  if (tid == 0) flags[0] = (atomicAdd(&g_done_bt[bt], 1) == NSPLIT - 1);
  __syncthreads();
  if (!flags[0]) return;
  __threadfence();   // acquire

  // ===== k_mfinal work (this block only) =====
  float* msV   = redf;          // [128]
  float* hsV   = redf + 128;    // [128]
  float* partV = redf + 256;    // [16]
  float* ddV   = redf + 280;    // [2]
  float* lgV   = redf + 284;    // [3]
  float* fin   = redf + 512;    // [8]

  float n1 = 0.f, n2 = 0.f;
  #pragma unroll
  for (int sp = 0; sp < NSPLIT; sp++){
    const float* p = g_mpart + ((size_t)bt*NSPLIT + sp)*MP_STRIDE;
    n1 += p[tid];
    n2 += p[TWOF + tid];
  }
  if (tid < 16){
    const float* p = g_mpart + ((size_t)bt*NSPLIT + tid)*MP_STRIDE;
    float d1 = p[2*TWOF], d2 = p[2*TWOF+1];
    #pragma unroll
    for (int o = 8; o > 0; o >>= 1){
      d1 += __shfl_down_sync(0xffffu, d1, o);
      d2 += __shfl_down_sync(0xffffu, d2, o);
    }
    if (tid == 0){ ddV[0] = d1; ddV[1] = d2; }
  }
  __syncthreads();

  float m1 = n1 / (ddV[0] + 1e-6f);
  float m2 = n2 / (ddV[1] + 1e-6f);
  float ma = (n1 + n2) / (ddV[0] + ddV[1] + 1e-6f);
  msV[tid] = ma;
  if (t == NT-1) d_out[MT_OFF + b*TWOF + tid] = ma;

  float wm1 = w_M[tid], wm2 = w_M[TWOF + tid];
  float q0 = warp_sum(m1*m1);
  float q1 = warp_sum(m1*wm1);
  float q2 = warp_sum(m2*m2);
  float q3 = warp_sum(m2*wm2);
  if (lane == 0){
    partV[warp] = q0; partV[4+warp] = q1; partV[8+warp] = q2; partV[12+warp] = q3;
  }
  __syncthreads();
  if (tid == 0){
    float sq1 = partV[0]+partV[1]+partV[2]+partV[3];
    float dt1 = partV[4]+partV[5]+partV[6]+partV[7];
    float sq2 = partV[8]+partV[9]+partV[10]+partV[11];
    float dt2 = partV[12]+partV[13]+partV[14]+partV[15];
    g_a1[bt] = dt1 / fmaxf(sqrtf(sq1), 1e-12f);
    g_a2[bt] = dt2 / fmaxf(sqrtf(sq2), 1e-12f);
  }

  if (t < TM1){
    float acc = sc_b1[tid];
    #pragma unroll 16
    for (int k = 0; k < TWOF; k++)
      acc = fmaf(g_W1T[k*TWOF + tid], msV[k], acc);
    hsV[tid] = fmaxf(acc, 0.f);
    __syncthreads();
    if (warp < 3){
      float p = 0.f;
      #pragma unroll
      for (int q = 0; q < 4; q++)
        p += hsV[lane + 32*q] * __ldg(&sc_W2[warp*TWOF + lane + 32*q]);
      p = warp_sum(p);
      if (lane == 0) lgV[warp] = p + sc_b2[warp];
    }
    __syncthreads();
    if (tid == 0){
      int cp = g_cnt_pos[b*TM1 + t], cn = g_cnt_neg[b*TM1 + t];
      float pr = (float)cp * (1.0f/NI);
      float nr = (float)cn * (1.0f/NI);
      int lbl = (pr >= 0.6f) ? 0 : ((nr >= 0.6f) ? 1 : 2);
      float mx = fmaxf(lgV[0], fmaxf(lgV[1], lgV[2]));
      float lse = logf(expf(lgV[0]-mx) + expf(lgV[1]-mx) + expf(lgV[2]-mx)) + mx;
      g_sync[b*TM1 + t] = lse - lgV[lbl];
    }
  }

  // ---- release a1/a2/sync; globally last block does the loss ----
  __syncthreads();
  __threadfence();
  if (tid == 0) flags[1] = (atomicAdd(&g_done_all, 1) == NB*NT - 1);
  __syncthreads();
  if (!flags[1]) return;
  __threadfence();   // acquire

  // ===== k_final work =====
  float bm = *b_M;
  float acc = 0.f;
  if (tid < NT*NB){
    int t1 = tid & (NT-1), bb = tid >> 5;
    float a1v = g_a1[bb*NT + t1];
    float sum = 0.f, pos = 0.f;
    #pragma unroll 4
    for (int t2 = 0; t2 < NT; t2++){
      float sc = a1v + g_a2[bb*NT + t2] + bm;
      sc = fminf(fmaxf(sc, -10.f), 10.f);
      float tw = 1.0f / (fabsf((float)(t1 - t2)) + 1.0f);
      float w = expf(sc * tw);
      sum += w;
      if (t2 == t1) pos = w;
    }
    acc = logf(sum + 1e-8f) - logf(pos);
  }
  acc = warp_sum(acc);
  if (lane == 0) fin[warp] = acc;
  float sv = (tid < NB*TM1) ? g_sync[tid] : 0.f;
  sv = warp_sum(sv);
  if (lane == 0) fin[4 + warp] = sv;
  __syncthreads();
  if (tid == 0){
    float lc = (fin[0]+fin[1]+fin[2]+fin[3]) * (1.0f/(NT*NB));
    float ls = (fin[4]+fin[5]+fin[6]+fin[7]) * (1.0f/(NB*TM1));
    d_out[LOSS_OFF] = lc + ls;
  }
}

// ---------------- launch ----------------
extern "C" void kernel_launch(void* const* d_in, const int* in_sizes, int n_in,
                              void* d_out, int out_size){
  const float* e_seq = (const float*)d_in[0];
  const float* Ws_w  = (const float*)d_in[2];
  const float* Ws_b  = (const float*)d_in[3];
  const float* Wiota = (const float*)d_in[4];
  const float* w_eta = (const float*)d_in[5];
  const float* w_M   = (const float*)d_in[6];
  const float* b_M   = (const float*)d_in[7];
  const float* sc_W1 = (const float*)d_in[8];
  const float* sc_b1 = (const float*)d_in[9];
  const float* sc_W2 = (const float*)d_in[10];
  const float* sc_b2 = (const float*)d_in[11];
  const int*  perms  = (const int*)d_in[12];
  const int*  cidx   = (const int*)d_in[13];
  float* out = (float*)d_out;

  k_pre<<<57, 256>>>(Wiota, w_eta, perms, sc_W1);
  k_main<<<dim3(NI/2, NB), 256>>>(e_seq, Ws_w, Ws_b, w_eta, cidx, out);
  k_msum<<<dim3(NB*NT, NSPLIT), 128>>>(e_seq, w_M, sc_b1, sc_W2, sc_b2, b_M, out);
}

// round 11
// speedup vs baseline: 1.1622x; 1.0667x over previous
#include <cuda_runtime.h>
#include <cuda_bf16.h>
#include <math.h>
#include <stdint.h>

#define NB 2
#define NT 32
#define NI 2048
#define NF 64
#define TWOF 128
#define NL 5
#define NSPLIT 16
#define CHUNK 128
#define TM1 31
#define MP_STRIDE 264

#define RT_SIZE (NB*NI*TWOF)          // 524288
#define MT_OFF  RT_SIZE
#define LOSS_OFF (RT_SIZE + NB*TWOF)  // 524544

#define ES_STRIDE 68
#define ES_TILE   (32*ES_STRIDE)
#define SS_STRIDE 33

// ---------------- scratch (device globals: allocation-free, zero-init at load) ----
__device__ __nv_bfloat16 g_rh[NB*NT*NI*NF];   // r_hist scratch (bf16)
__device__ float g_eta[NB*NT*NI];
__device__ float g_W1T[TWOF*TWOF];            // sc_W1 transposed
__device__ unsigned char g_member[NT*NI];
__device__ int   g_cnt_pos[NB*TM1];           // self-zeroing (consumed+reset by tail)
__device__ int   g_cnt_neg[NB*TM1];
__device__ float g_mpart[NB*NT*NSPLIT*MP_STRIDE];
__device__ float g_a1[NB*NT];
__device__ float g_a2[NB*NT];
__device__ float g_sync[NB*TM1];
__device__ int   g_done_bt[NB*NT];            // self-zeroing
__device__ int   g_done_all;                  // self-zeroing

__device__ __forceinline__ float warp_sum(float v){
  #pragma unroll
  for (int o = 16; o > 0; o >>= 1) v += __shfl_xor_sync(0xffffffffu, v, o);
  return v;
}

__device__ __forceinline__ uint32_t f2tf32(float x){
  uint32_t r;
  asm("cvt.rna.tf32.f32 %0, %1;" : "=r"(r) : "f"(x));
  return r;
}

__device__ __forceinline__ void mma_tf32(float c[4], const uint32_t a[4],
                                         uint32_t b0, uint32_t b1){
  asm("mma.sync.aligned.m16n8k8.row.col.f32.tf32.tf32.f32 "
      "{%0,%1,%2,%3},{%4,%5,%6,%7},{%8,%9},{%0,%1,%2,%3};"
      : "+f"(c[0]), "+f"(c[1]), "+f"(c[2]), "+f"(c[3])
      : "r"(a[0]), "r"(a[1]), "r"(a[2]), "r"(a[3]), "r"(b0), "r"(b1));
}

// ---------------- K_main: main blocks (b<NB) + prep blocks (b==NB) ----------------
__global__ __launch_bounds__(256) void k_main(
    const float* __restrict__ e_seq, const float* __restrict__ Ws_w,
    const float* __restrict__ Ws_b, const float* __restrict__ w_eta,
    const int* __restrict__ close_idx_p, const float* __restrict__ Wiota,
    const int* __restrict__ perms, const float* __restrict__ sc_W1,
    float* __restrict__ d_out)
{
  __shared__ float smemA[64*ES_STRIDE];   // 17408B: Wsm -> Ks  (prep: transpose tile)
  __shared__ float Esf[2*ES_TILE];        // 17408B
  __shared__ float Ss[2*32*SS_STRIDE];    //  8448B
  __shared__ float ciS[2];

  int b = blockIdx.y;
  int tid = threadIdx.x;

  // ===== prep blocks: member scatter + W1T transpose (run concurrently w/ main) =====
  if (b == NB){
    int bx = blockIdx.x;
    if (bx < NT){
      int t = bx;
      for (int j = tid; j < NI; j += 256){
        int p = perms[t*NI + j];
        g_member[t*NI + p] = (unsigned char)(j >= NI/2);
      }
    } else if (bx < NT + 16){
      // transpose 32x32 tile (r,c) of sc_W1 through smem (coalesced both ways)
      int p = bx - NT;
      int r = p >> 2, cc = p & 3;
      float* tileT = smemA;   // [32][33]
      for (int x = tid; x < 1024; x += 256){
        int row = x >> 5, col = x & 31;
        tileT[col*33 + row] = sc_W1[(32*r + row)*TWOF + 32*cc + col];
      }
      __syncthreads();
      for (int x = tid; x < 1024; x += 256){
        int row = x >> 5, col = x & 31;
        g_W1T[(32*cc + row)*TWOF + 32*r + col] = tileT[row*33 + col];
      }
    }
    return;
  }

  // ===== main blocks =====
  int i0 = blockIdx.x * 2;
  int warp = tid >> 5, lane = tid & 31;
  int g  = lane >> 2, tg = lane & 3;

  float* Wsm = smemA;
  float* Ks  = smemA;

  // per-tile iota dot (replaces g_c)
  if (warp < 2){
    const float4* wi = (const float4*)(Wiota + (size_t)(i0 + warp)*TWOF);
    const float4* wev = (const float4*)w_eta;
    float4 a = wi[lane], bv = wev[lane];
    float s = a.x*bv.x + a.y*bv.y + a.z*bv.z + a.w*bv.w;
    s = warp_sum(s);
    if (lane == 0) ciS[warp] = s;
  }

  {
    const float4* wg = (const float4*)Ws_w;
    #pragma unroll
    for (int x = tid; x < 1024; x += 256){
      int fo = x >> 4, c = x & 15;
      ((float4*)(Wsm + fo*ES_STRIDE))[c] = wg[x];
    }
  }
  {
    #pragma unroll
    for (int x = tid; x < 1024; x += 256){
      int tile = x >> 9, t = (x >> 4) & 31, c = x & 15;
      const float4* eg = (const float4*)(e_seq + ((size_t)b*NT*NI + (i0+tile))*NF);
      ((float4*)(Esf + (tile*32 + t)*ES_STRIDE))[c] = eg[(size_t)t*(NI*16) + c];
    }
  }
  __syncthreads();

  // return-sign counts (atomic; counters pre-zeroed by previous consume)
  if (warp < 2 && lane < TM1){
    int cidx = *close_idx_p;
    const float* ef = Esf + warp*ES_TILE;
    float c0 = ef[lane*ES_STRIDE + cidx];
    float c1 = ef[(lane+1)*ES_STRIDE + cidx];
    float r = c1 / (c0 + 1e-8f);
    if (r > 1.0f)      atomicAdd(&g_cnt_pos[b*TM1 + lane], 1);
    else if (r < 1.0f) atomicAdd(&g_cnt_neg[b*TM1 + lane], 1);
  }

  // ---- k = e @ Ws^T + b via tf32 mma, hi/lo split ----
  float c[4][4];
  {
    int tl = warp >> 2, mt = (warp >> 1) & 1, nh = warp & 1;
    const float* Et = Esf + tl*ES_TILE + (mt*16)*ES_STRIDE;

    #pragma unroll
    for (int nt = 0; nt < 4; nt++)
      #pragma unroll
      for (int q = 0; q < 4; q++) c[nt][q] = 0.f;

    #pragma unroll
    for (int ks = 0; ks < 8; ks++){
      int k0 = ks*8;
      float af[4];
      af[0] = Et[g*ES_STRIDE + k0 + tg];
      af[1] = Et[(g+8)*ES_STRIDE + k0 + tg];
      af[2] = Et[g*ES_STRIDE + k0 + tg + 4];
      af[3] = Et[(g+8)*ES_STRIDE + k0 + tg + 4];
      uint32_t ah[4], al[4];
      #pragma unroll
      for (int q = 0; q < 4; q++){
        ah[q] = f2tf32(af[q]);
        al[q] = f2tf32(af[q] - __uint_as_float(ah[q]));
      }
      #pragma unroll
      for (int nt = 0; nt < 4; nt++){
        int n0 = nh*32 + nt*8;
        float b0f = Wsm[(n0+g)*ES_STRIDE + k0 + tg];
        float b1f = Wsm[(n0+g)*ES_STRIDE + k0 + tg + 4];
        uint32_t bh0 = f2tf32(b0f), bh1 = f2tf32(b1f);
        uint32_t bl0 = f2tf32(b0f - __uint_as_float(bh0));
        uint32_t bl1 = f2tf32(b1f - __uint_as_float(bh1));
        mma_tf32(c[nt], ah, bh0, bh1);
        mma_tf32(c[nt], ah, bl0, bl1);
        mma_tf32(c[nt], al, bh0, bh1);
      }
    }
  }
  __syncthreads();

  {
    int tl = warp >> 2, mt = (warp >> 1) & 1, nh = warp & 1;
    #pragma unroll
    for (int nt = 0; nt < 4; nt++){
      int n0 = nh*32 + nt*8;
      int col = n0 + 2*tg;
      float bb0 = __ldg(Ws_b + col), bb1 = __ldg(Ws_b + col + 1);
      int r0 = mt*16 + g;
      float* k0p = Ks + (tl*32 + r0)*ES_STRIDE + col;
      float* k1p = Ks + (tl*32 + r0 + 8)*ES_STRIDE + col;
      k0p[0] = c[nt][0] + bb0; k0p[1] = c[nt][1] + bb1;
      k1p[0] = c[nt][2] + bb0; k1p[1] = c[nt][3] + bb1;
    }
  }
  __syncthreads();

  // ---- scores S = (K K^T)/8 per tile ----
  {
    int stile = warp >> 2;
    int smt   = (warp >> 1) & 1;
    int snh   = warp & 1;
    const float* Km = Ks + (stile*32 + smt*16)*ES_STRIDE;
    const float* Kn = Ks + stile*32*ES_STRIDE;

    float sc[2][4];
    #pragma unroll
    for (int u = 0; u < 2; u++)
      #pragma unroll
      for (int q = 0; q < 4; q++) sc[u][q] = 0.f;

    #pragma unroll
    for (int ks = 0; ks < 8; ks++){
      int k0 = ks*8;
      float af[4];
      af[0] = Km[g*ES_STRIDE + k0 + tg];
      af[1] = Km[(g+8)*ES_STRIDE + k0 + tg];
      af[2] = Km[g*ES_STRIDE + k0 + tg + 4];
      af[3] = Km[(g+8)*ES_STRIDE + k0 + tg + 4];
      uint32_t ah[4], al[4];
      #pragma unroll
      for (int q = 0; q < 4; q++){
        ah[q] = f2tf32(af[q]);
        al[q] = f2tf32(af[q] - __uint_as_float(ah[q]));
      }
      #pragma unroll
      for (int u = 0; u < 2; u++){
        int n0 = (2*snh + u)*8;
        float b0f = Kn[(n0+g)*ES_STRIDE + k0 + tg];
        float b1f = Kn[(n0+g)*ES_STRIDE + k0 + tg + 4];
        uint32_t bh0 = f2tf32(b0f), bh1 = f2tf32(b1f);
        uint32_t bl0 = f2tf32(b0f - __uint_as_float(bh0));
        uint32_t bl1 = f2tf32(b1f - __uint_as_float(bh1));
        mma_tf32(sc[u], ah, bh0, bh1);
        mma_tf32(sc[u], ah, bl0, bl1);
        mma_tf32(sc[u], al, bh0, bh1);
      }
    }
    #pragma unroll
    for (int u = 0; u < 2; u++){
      int col = (2*snh + u)*8 + 2*tg;
      int r0 = smt*16 + g;
      float* s0 = Ss + (stile*32 + r0)*SS_STRIDE + col;
      float* s1 = Ss + (stile*32 + r0 + 8)*SS_STRIDE + col;
      s0[0] = sc[u][0]*0.125f; s0[1] = sc[u][1]*0.125f;
      s1[0] = sc[u][2]*0.125f; s1[1] = sc[u][3]*0.125f;
    }
  }
  __syncthreads();

  float we0 = __ldg(w_eta + lane),      we1 = __ldg(w_eta + 32 + lane);
  float we2 = __ldg(w_eta + 64 + lane), we3 = __ldg(w_eta + 96 + lane);

  #pragma unroll
  for (int tile = 0; tile < 2; tile++){
    int i = i0 + tile;
    float ci = ciS[tile];
    const float* Et = Esf + tile*ES_TILE;

    for (int tt = warp; tt < NT; tt += 8){
      const float* Srow = Ss + (tile*32 + tt)*SS_STRIDE;
      float s[NL];
      #pragma unroll
      for (int l = 0; l < NL; l++){
        int t2 = tt - 4 + l;
        s[l] = (t2 >= 0) ? Srow[t2] : -1e30f;
      }
      float mx = s[0];
      #pragma unroll
      for (int l = 1; l < NL; l++) mx = fmaxf(mx, s[l]);
      float pe[NL], psum = 0.f;
      #pragma unroll
      for (int l = 0; l < NL; l++){ pe[l] = expf(s[l] - mx); psum += pe[l]; }
      float inv = 1.0f / psum;
      float rh0 = 0.f, rh1 = 0.f;
      #pragma unroll
      for (int l = 0; l < NL; l++){
        int t2 = tt - 4 + l; if (t2 < 0) t2 = 0;
        float a = pe[l] * inv;
        rh0 += a * Et[t2*ES_STRIDE + lane];
        rh1 += a * Et[t2*ES_STRIDE + 32 + lane];
      }
      size_t rbase = (((size_t)b*NT + tt)*NI + i)*NF;
      g_rh[rbase + lane]      = __float2bfloat16(rh0);
      g_rh[rbase + 32 + lane] = __float2bfloat16(rh1);

      float e0 = Et[tt*ES_STRIDE + lane], e1 = Et[tt*ES_STRIDE + 32 + lane];
      float d = e0*we0 + e1*we1 + rh0*we2 + rh1*we3;
      d = warp_sum(d);
      float eta = fmaxf(d + ci, 0.f);
      if (lane == 0) g_eta[((size_t)b*NT + tt)*NI + i] = eta;

      if (tt == NT-1){
        float* ro = d_out + ((size_t)b*NI + i)*TWOF;
        ro[lane] = e0; ro[32+lane] = e1; ro[64+lane] = rh0; ro[96+lane] = rh1;
      }
    }
  }
}

// ---------------- K_msum + fused tail ----------------
__global__ __launch_bounds__(128) void k_msum(
    const float* __restrict__ e_seq,
    const float* __restrict__ w_M,
    const float* __restrict__ sc_b1,
    const float* __restrict__ sc_W2, const float* __restrict__ sc_b2,
    const float* __restrict__ b_M,
    float* __restrict__ d_out)
{
  int bt = blockIdx.x;
  int b = bt / NT, t = bt % NT;
  int s  = blockIdx.y;
  int tid = threadIdx.x;
  int warp = tid >> 5, lane = tid & 31;
  __shared__ float eta_s[CHUNK];
  __shared__ float w2_s[CHUNK];
  __shared__ float4 red[256];
  __shared__ int flags[2];
  float* redf = (float*)red;

  int i0 = s * CHUNK;
  if (tid < CHUNK){
    float e = g_eta[(size_t)bt*NI + i0 + tid];
    eta_s[tid] = e;
    w2_s[tid]  = g_member[t*NI + i0 + tid] ? e : 0.f;
  }
  __syncthreads();

  int fq = tid & 31;
  int jb = tid >> 5;
  bool hi = fq >= 16;
  int c = hi ? fq - 16 : fq;
  float4 a1 = make_float4(0.f,0.f,0.f,0.f);
  float4 a2 = make_float4(0.f,0.f,0.f,0.f);

  if (!hi){
    const float4* base = (const float4*)(e_seq + ((size_t)bt*NI + i0)*NF);
    #pragma unroll 8
    for (int j = jb; j < CHUNK; j += 4){
      float4 r = base[(size_t)j*16 + c];
      float w2 = w2_s[j], w1 = eta_s[j] - w2;
      a1.x += w1*r.x; a1.y += w1*r.y; a1.z += w1*r.z; a1.w += w1*r.w;
      a2.x += w2*r.x; a2.y += w2*r.y; a2.z += w2*r.z; a2.w += w2*r.w;
    }
  } else {
    const __nv_bfloat162* base =
        (const __nv_bfloat162*)(g_rh + ((size_t)bt*NI + i0)*NF);
    #pragma unroll 8
    for (int j = jb; j < CHUNK; j += 4){
      __nv_bfloat162 p0 = base[(size_t)j*32 + 2*c];
      __nv_bfloat162 p1 = base[(size_t)j*32 + 2*c + 1];
      float4 r;
      r.x = __bfloat162float(p0.x); r.y = __bfloat162float(p0.y);
      r.z = __bfloat162float(p1.x); r.w = __bfloat162float(p1.y);
      float w2 = w2_s[j], w1 = eta_s[j] - w2;
      a1.x += w1*r.x; a1.y += w1*r.y; a1.z += w1*r.z; a1.w += w1*r.w;
      a2.x += w2*r.x; a2.y += w2*r.y; a2.z += w2*r.z; a2.w += w2*r.w;
    }
  }
  red[tid] = a1; red[128 + tid] = a2;
  __syncthreads();

  float* op = g_mpart + ((size_t)bt*NSPLIT + s)*MP_STRIDE;
  if (tid < 64){
    int which = tid >> 5;
    int q = tid & 31;
    float4 sum = red[which*128 + q];
    #pragma unroll
    for (int g2 = 1; g2 < 4; g2++){
      float4 v = red[which*128 + 32*g2 + q];
      sum.x += v.x; sum.y += v.y; sum.z += v.z; sum.w += v.w;
    }
    ((float4*)(op + which*TWOF))[q] = sum;
  } else if (tid < 96){
    int l = tid - 64;
    float d1 = 0.f, d2 = 0.f;
    #pragma unroll
    for (int j = l; j < CHUNK; j += 32){ float w2 = w2_s[j]; d2 += w2; d1 += eta_s[j] - w2; }
    d1 = warp_sum(d1);
    d2 = warp_sum(d2);
    if (l == 0){ op[2*TWOF] = d1; op[2*TWOF+1] = d2; }
  }

  // ---- release partials; last block per bt does the combine ----
  __syncthreads();
  __threadfence();
  if (tid == 0) flags[0] = (atomicAdd(&g_done_bt[bt], 1) == NSPLIT - 1);
  __syncthreads();
  if (!flags[0]) return;
  __threadfence();   // acquire
  if (tid == 0) g_done_bt[bt] = 0;   // reset for next replay

  // ===== mfinal work =====
  float* msV   = redf;
  float* hsV   = redf + 128;
  float* partV = redf + 256;
  float* ddV   = redf + 280;
  float* lgV   = redf + 284;
  float* fin   = redf + 512;

  float n1 = 0.f, n2 = 0.f;
  #pragma unroll
  for (int sp = 0; sp < NSPLIT; sp++){
    const float* p = g_mpart + ((size_t)bt*NSPLIT + sp)*MP_STRIDE;
    n1 += p[tid];
    n2 += p[TWOF + tid];
  }
  if (tid < 16){
    const float* p = g_mpart + ((size_t)bt*NSPLIT + tid)*MP_STRIDE;
    float d1 = p[2*TWOF], d2 = p[2*TWOF+1];
    #pragma unroll
    for (int o = 8; o > 0; o >>= 1){
      d1 += __shfl_down_sync(0xffffu, d1, o);
      d2 += __shfl_down_sync(0xffffu, d2, o);
    }
    if (tid == 0){ ddV[0] = d1; ddV[1] = d2; }
  }
  __syncthreads();

  float m1 = n1 / (ddV[0] + 1e-6f);
  float m2 = n2 / (ddV[1] + 1e-6f);
  float ma = (n1 + n2) / (ddV[0] + ddV[1] + 1e-6f);
  msV[tid] = ma;
  if (t == NT-1) d_out[MT_OFF + b*TWOF + tid] = ma;

  float wm1 = w_M[tid], wm2 = w_M[TWOF + tid];
  float q0 = warp_sum(m1*m1);
  float q1 = warp_sum(m1*wm1);
  float q2 = warp_sum(m2*m2);
  float q3 = warp_sum(m2*wm2);
  if (lane == 0){
    partV[warp] = q0; partV[4+warp] = q1; partV[8+warp] = q2; partV[12+warp] = q3;
  }
  __syncthreads();
  if (tid == 0){
    float sq1 = partV[0]+partV[1]+partV[2]+partV[3];
    float dt1 = partV[4]+partV[5]+partV[6]+partV[7];
    float sq2 = partV[8]+partV[9]+partV[10]+partV[11];
    float dt2 = partV[12]+partV[13]+partV[14]+partV[15];
    g_a1[bt] = dt1 / fmaxf(sqrtf(sq1), 1e-12f);
    g_a2[bt] = dt2 / fmaxf(sqrtf(sq2), 1e-12f);
  }

  if (t < TM1){
    float acc = sc_b1[tid];
    #pragma unroll 16
    for (int k = 0; k < TWOF; k++)
      acc = fmaf(g_W1T[k*TWOF + tid], msV[k], acc);
    hsV[tid] = fmaxf(acc, 0.f);
    __syncthreads();
    if (warp < 3){
      float p = 0.f;
      #pragma unroll
      for (int q = 0; q < 4; q++)
        p += hsV[lane + 32*q] * __ldg(&sc_W2[warp*TWOF + lane + 32*q]);
      p = warp_sum(p);
      if (lane == 0) lgV[warp] = p + sc_b2[warp];
    }
    __syncthreads();
    if (tid == 0){
      int cp = g_cnt_pos[b*TM1 + t], cn = g_cnt_neg[b*TM1 + t];
      g_cnt_pos[b*TM1 + t] = 0;   // consume + reset for next replay
      g_cnt_neg[b*TM1 + t] = 0;
      float pr = (float)cp * (1.0f/NI);
      float nr = (float)cn * (1.0f/NI);
      int lbl = (pr >= 0.6f) ? 0 : ((nr >= 0.6f) ? 1 : 2);
      float mx = fmaxf(lgV[0], fmaxf(lgV[1], lgV[2]));
      float lse = logf(expf(lgV[0]-mx) + expf(lgV[1]-mx) + expf(lgV[2]-mx)) + mx;
      g_sync[b*TM1 + t] = lse - lgV[lbl];
    }
  }

  // ---- release; globally last block does the loss ----
  __syncthreads();
  __threadfence();
  if (tid == 0) flags[1] = (atomicAdd(&g_done_all, 1) == NB*NT - 1);
  __syncthreads();
  if (!flags[1]) return;
  __threadfence();   // acquire
  if (tid == 0) g_done_all = 0;   // reset for next replay

  // ===== final loss =====
  float bm = *b_M;
  float acc = 0.f;
  if (tid < NT*NB){
    int t1 = tid & (NT-1), bb = tid >> 5;
    float a1v = g_a1[bb*NT + t1];
    float sum = 0.f, pos = 0.f;
    #pragma unroll 4
    for (int t2 = 0; t2 < NT; t2++){
      float sc = a1v + g_a2[bb*NT + t2] + bm;
      sc = fminf(fmaxf(sc, -10.f), 10.f);
      float tw = 1.0f / (fabsf((float)(t1 - t2)) + 1.0f);
      float w = expf(sc * tw);
      sum += w;
      if (t2 == t1) pos = w;
    }
    acc = logf(sum + 1e-8f) - logf(pos);
  }
  acc = warp_sum(acc);
  if (lane == 0) fin[warp] = acc;
  float sv = (tid < NB*TM1) ? g_sync[tid] : 0.f;
  sv = warp_sum(sv);
  if (lane == 0) fin[4 + warp] = sv;
  __syncthreads();
  if (tid == 0){
    float lc = (fin[0]+fin[1]+fin[2]+fin[3]) * (1.0f/(NT*NB));
    float ls = (fin[4]+fin[5]+fin[6]+fin[7]) * (1.0f/(NB*TM1));
    d_out[LOSS_OFF] = lc + ls;
  }
}

// ---------------- launch ----------------
extern "C" void kernel_launch(void* const* d_in, const int* in_sizes, int n_in,
                              void* d_out, int out_size){
  const float* e_seq = (const float*)d_in[0];
  const float* Ws_w  = (const float*)d_in[2];
  const float* Ws_b  = (const float*)d_in[3];
  const float* Wiota = (const float*)d_in[4];
  const float* w_eta = (const float*)d_in[5];
  const float* w_M   = (const float*)d_in[6];
  const float* b_M   = (const float*)d_in[7];
  const float* sc_W1 = (const float*)d_in[8];
  const float* sc_b1 = (const float*)d_in[9];
  const float* sc_W2 = (const float*)d_in[10];
  const float* sc_b2 = (const float*)d_in[11];
  const int*  perms  = (const int*)d_in[12];
  const int*  cidx   = (const int*)d_in[13];
  float* out = (float*)d_out;

  k_main<<<dim3(NI/2, NB+1), 256>>>(e_seq, Ws_w, Ws_b, w_eta, cidx,
                                    Wiota, perms, sc_W1, out);
  k_msum<<<dim3(NB*NT, NSPLIT), 128>>>(e_seq, w_M, sc_b1, sc_W2, sc_b2, b_M, out);
}